// round 3
// baseline (speedup 1.0000x reference)
#include <cuda_runtime.h>
#include <cstdint>

#define NNODES 25000
#define NEDGES 400000
#define FIN 128
#define FE 16
#define CW 32
#define UE 4

// persistent scratch (no allocs allowed)
__device__ float g_h[NNODES * CW];     // lrelu(x@W_in + b_in)
__device__ float g_aggr[NNODES * CW];  // segment-sum accumulator
__device__ int g_is64;                 // edge_index dtype flag

__device__ __forceinline__ float lrelu(float v) {
    return fmaxf(v, 0.f) + 0.01f * fminf(v, 0.f);
}

// ---- packed f32x2 helpers (FFMA2 path: full-rate fp32 on sm_103a) ----
__device__ __forceinline__ unsigned long long pack2(float a, float b) {
    unsigned long long r;
    asm("mov.b64 %0,{%1,%2};" : "=l"(r) : "f"(a), "f"(b));
    return r;
}
__device__ __forceinline__ void unpack2(unsigned long long p, float& a, float& b) {
    asm("mov.b64 {%0,%1},%2;" : "=f"(a), "=f"(b) : "l"(p));
}
__device__ __forceinline__ unsigned long long ffma2(unsigned long long a,
                                                    unsigned long long b,
                                                    unsigned long long c) {
    unsigned long long d;
    asm("fma.rn.f32x2 %0,%1,%2,%3;" : "=l"(d) : "l"(a), "l"(b), "l"(c));
    return d;
}
__device__ __forceinline__ unsigned long long fmul2(unsigned long long a,
                                                    unsigned long long b) {
    unsigned long long d;
    asm("mul.rn.f32x2 %0,%1,%2;" : "=l"(d) : "l"(a), "l"(b));
    return d;
}

// ---- kernel 0: detect int64 vs int32 edge_index ----
__global__ void k_detect(const void* ei) {
    if (threadIdx.x == 0) {
        const unsigned long long* p = (const unsigned long long*)ei;
        int ok = 1;
        #pragma unroll
        for (int i = 0; i < 16; i++) {
            if (p[i] >= (unsigned long long)NNODES) ok = 0;
        }
        g_is64 = ok;  // int32 data read as u64 has a nonzero high word w.h.p.
    }
}

// ---- kernel 1: zero the aggregation buffer ----
__global__ void k_zero() {
    int i = blockIdx.x * blockDim.x + threadIdx.x;
    if (i < NNODES * CW) g_aggr[i] = 0.f;
}

// ---- kernel 2: h = lrelu(x @ W_in + b_in), warp = 2 nodes, lane = channel ----
__global__ void k_in(const float* __restrict__ x, const float* __restrict__ Win,
                     const float* __restrict__ bin) {
    __shared__ float Ws[FIN * CW];
    __shared__ float bs[CW];
    for (int i = threadIdx.x; i < FIN * CW; i += blockDim.x) Ws[i] = Win[i];
    if (threadIdx.x < CW) bs[threadIdx.x] = bin[threadIdx.x];
    __syncthreads();

    int gw = (blockIdx.x * blockDim.x + threadIdx.x) >> 5;
    int lane = threadIdx.x & 31;
    int n0 = gw * 2;
    if (n0 >= NNODES) return;
    bool two = (n0 + 1) < NNODES;

    float acc0 = bs[lane], acc1 = bs[lane];
    const float4* x0 = (const float4*)(x + (size_t)n0 * FIN);
    const float4* x1 = (const float4*)(x + (size_t)(two ? n0 + 1 : n0) * FIN);
    #pragma unroll 8
    for (int k4 = 0; k4 < FIN / 4; k4++) {
        float4 a = x0[k4], b = x1[k4];
        float w0 = Ws[(k4 * 4 + 0) * CW + lane];
        float w1 = Ws[(k4 * 4 + 1) * CW + lane];
        float w2 = Ws[(k4 * 4 + 2) * CW + lane];
        float w3 = Ws[(k4 * 4 + 3) * CW + lane];
        acc0 = fmaf(a.x, w0, acc0); acc0 = fmaf(a.y, w1, acc0);
        acc0 = fmaf(a.z, w2, acc0); acc0 = fmaf(a.w, w3, acc0);
        acc1 = fmaf(b.x, w0, acc1); acc1 = fmaf(b.y, w1, acc1);
        acc1 = fmaf(b.z, w2, acc1); acc1 = fmaf(b.w, w3, acc1);
    }
    g_h[n0 * CW + lane] = lrelu(acc0);
    if (two) g_h[(n0 + 1) * CW + lane] = lrelu(acc1);
}

// ---- kernel 3: fused per-edge NNConv message + scatter-add ----
// lane = output channel o; channel-paired f32x2 math; 4 edges per warp-iter.
// msg_o = sum_c h[src][c] * lrelu( sum_f ea[f]*W_edge[f][c*32+o] + b_edge[c*32+o] )
__global__ void __launch_bounds__(128) k_edge(const void* __restrict__ eidx,
                                              const float* __restrict__ eattr,
                                              const float* __restrict__ Wedge,
                                              const float* __restrict__ bedge) {
    extern __shared__ float sh[];
    unsigned long long* Wq = (unsigned long long*)sh;   // [16 f][16 c2][32 o] float2 pairs = 64KB
    unsigned long long* bq = Wq + FE * 16 * 32;         // [16 c2][32 o] pairs = 4KB
    float* hst = (float*)(bq + 16 * 32);                // per-warp staged h rows: 4 warps * 4 edges * 32

    // build channel-paired W: Wq[(f*16+c2)*32+o] = (W[f][2c2*32+o], W[f][(2c2+1)*32+o])
    for (int p = threadIdx.x; p < FE * 16 * 32; p += blockDim.x) {
        int f = p >> 9; int r = p & 511; int c2 = r >> 5; int o = r & 31;
        Wq[p] = pack2(Wedge[f * 1024 + (2 * c2) * 32 + o],
                      Wedge[f * 1024 + (2 * c2 + 1) * 32 + o]);
    }
    for (int p = threadIdx.x; p < 16 * 32; p += blockDim.x) {
        int c2 = p >> 5; int o = p & 31;
        bq[p] = pack2(bedge[(2 * c2) * 32 + o], bedge[(2 * c2 + 1) * 32 + o]);
    }
    __syncthreads();

    const int lane = threadIdx.x & 31;
    const int warp = threadIdx.x >> 5;
    const long long* e64 = (const long long*)eidx;
    const int* e32 = (const int*)eidx;
    const int is64 = g_is64;
    float* hw = hst + warp * (UE * 32);
    const unsigned long long* hq = (const unsigned long long*)hw;

    const unsigned long long K0505 = pack2(0.505f, 0.505f);
    const unsigned long long K0495 = pack2(0.495f, 0.495f);
    const unsigned long long MABS = 0x7FFFFFFF7FFFFFFFULL;

    const int ngroups = NEDGES / 16;  // 16 edges per block-iter (4 warps x 4)
    for (int g = blockIdx.x; g < ngroups; g += gridDim.x) {
        const int ebase = g * 16 + warp * UE;
        int dsts[UE];
        unsigned long long ea2[UE][FE];
        #pragma unroll
        for (int u = 0; u < UE; u++) {
            const int e = ebase + u;
            int s, d;
            if (is64) { s = (int)e64[e]; d = (int)e64[NEDGES + e]; }
            else      { s = e32[e];      d = e32[NEDGES + e]; }
            dsts[u] = d;
            hw[u * 32 + lane] = g_h[(size_t)s * CW + lane];  // stage source row
            const float4* ep = (const float4*)(eattr + (size_t)e * FE);
            #pragma unroll
            for (int q = 0; q < 4; q++) {
                float4 v = ep[q];
                ea2[u][q * 4 + 0] = pack2(v.x, v.x);
                ea2[u][q * 4 + 1] = pack2(v.y, v.y);
                ea2[u][q * 4 + 2] = pack2(v.z, v.z);
                ea2[u][q * 4 + 3] = pack2(v.w, v.w);
            }
        }
        __syncwarp();

        unsigned long long msg[UE];
        #pragma unroll
        for (int u = 0; u < UE; u++) msg[u] = 0ULL;

        for (int c2 = 0; c2 < 16; c2++) {
            unsigned long long z[UE];
            unsigned long long bini = bq[c2 * 32 + lane];
            #pragma unroll
            for (int u = 0; u < UE; u++) z[u] = bini;
            #pragma unroll
            for (int f = 0; f < FE; f++) {
                unsigned long long w2 = Wq[(f * 16 + c2) * 32 + lane];
                #pragma unroll
                for (int u = 0; u < UE; u++) z[u] = ffma2(ea2[u][f], w2, z[u]);
            }
            // packed leaky-relu: t = 0.505*z + 0.495*|z|, then msg += h2 * t
            #pragma unroll
            for (int u = 0; u < UE; u++) {
                unsigned long long t = ffma2(K0495, z[u] & MABS, fmul2(K0505, z[u]));
                msg[u] = ffma2(hq[u * 16 + c2], t, msg[u]);
            }
        }
        #pragma unroll
        for (int u = 0; u < UE; u++) {
            float a, b;
            unpack2(msg[u], a, b);
            atomicAdd(&g_aggr[(size_t)dsts[u] * CW + lane], a + b);
        }
        __syncwarp();  // hw reused next group (cross-lane reads)
    }
}

// ---- kernel 4: out = lrelu(aggr + h@W_root + b_conv) @ W_out + b_out ----
__global__ void k_out(const float* __restrict__ Wr, const float* __restrict__ bc,
                      const float* __restrict__ Wo, const float* __restrict__ bo,
                      float* __restrict__ out) {
    __shared__ float Wrs[CW * CW];
    __shared__ float Wos[CW];
    __shared__ float bcs[CW];
    for (int i = threadIdx.x; i < CW * CW; i += blockDim.x) Wrs[i] = Wr[i];
    if (threadIdx.x < CW) { Wos[threadIdx.x] = Wo[threadIdx.x]; bcs[threadIdx.x] = bc[threadIdx.x]; }
    __syncthreads();

    int gw = (blockIdx.x * blockDim.x + threadIdx.x) >> 5;
    int lane = threadIdx.x & 31;
    if (gw >= NNODES) return;

    float r = g_aggr[(size_t)gw * CW + lane] + bcs[lane];
    const float4* hp = (const float4*)(g_h + (size_t)gw * CW);
    #pragma unroll
    for (int c4 = 0; c4 < CW / 4; c4++) {
        float4 h4 = hp[c4];
        int c = c4 * 4;
        r = fmaf(h4.x, Wrs[(c + 0) * CW + lane], r);
        r = fmaf(h4.y, Wrs[(c + 1) * CW + lane], r);
        r = fmaf(h4.z, Wrs[(c + 2) * CW + lane], r);
        r = fmaf(h4.w, Wrs[(c + 3) * CW + lane], r);
    }
    float t = lrelu(r) * Wos[lane];
    #pragma unroll
    for (int off = 16; off; off >>= 1) t += __shfl_xor_sync(0xFFFFFFFFu, t, off);
    if (lane == 0) out[gw] = t + bo[0];
}

extern "C" void kernel_launch(void* const* d_in, const int* in_sizes, int n_in,
                              void* d_out, int out_size) {
    const float* x     = (const float*)d_in[0];
    const void*  ei    = d_in[1];
    const float* ea    = (const float*)d_in[2];
    const float* Win   = (const float*)d_in[3];
    const float* bin   = (const float*)d_in[4];
    const float* Wedge = (const float*)d_in[5];
    const float* bedge = (const float*)d_in[6];
    const float* Wroot = (const float*)d_in[7];
    const float* bconv = (const float*)d_in[8];
    const float* Wout  = (const float*)d_in[9];
    const float* bout  = (const float*)d_in[10];
    float* out = (float*)d_out;

    const int smem = (FE * 16 * 32 + 16 * 32) * 8 + 4 * UE * 32 * 4;  // 71680 B
    cudaFuncSetAttribute(k_edge, cudaFuncAttributeMaxDynamicSharedMemorySize, smem);

    k_detect<<<1, 32>>>(ei);
    k_zero<<<(NNODES * CW + 255) / 256, 256>>>();
    k_in<<<(((NNODES + 1) / 2) * 32 + 255) / 256, 256>>>(x, Win, bin);
    k_edge<<<296, 128, smem>>>(ei, ea, Wedge, bedge);
    k_out<<<(NNODES * 32 + 255) / 256, 256>>>(Wroot, bconv, Wout, bout, out);
}

// round 5
// speedup vs baseline: 1.1041x; 1.1041x over previous
#include <cuda_runtime.h>
#include <cstdint>

#define NNODES 25000
#define NEDGES 400000
#define FIN 128
#define FE 16
#define CW 32
#define UE 4
#define WPB 16   // warps per block (512 threads)

// persistent scratch (no allocs allowed)
__device__ float g_h[NNODES * CW];     // lrelu(x@W_in + b_in)
__device__ float g_aggr[NNODES * CW];  // segment-sum accumulator
__device__ int g_is64;                 // edge_index dtype flag

__device__ __forceinline__ float lrelu(float v) {
    return fmaxf(v, 0.f) + 0.01f * fminf(v, 0.f);
}

// ---- packed f32x2 helpers (FFMA2 path: full-rate fp32 on sm_103a) ----
__device__ __forceinline__ unsigned long long pack2(float a, float b) {
    unsigned long long r;
    asm("mov.b64 %0,{%1,%2};" : "=l"(r) : "f"(a), "f"(b));
    return r;
}
__device__ __forceinline__ void unpack2(unsigned long long p, float& a, float& b) {
    asm("mov.b64 {%0,%1},%2;" : "=f"(a), "=f"(b) : "l"(p));
}
__device__ __forceinline__ unsigned long long ffma2(unsigned long long a,
                                                    unsigned long long b,
                                                    unsigned long long c) {
    unsigned long long d;
    asm("fma.rn.f32x2 %0,%1,%2,%3;" : "=l"(d) : "l"(a), "l"(b), "l"(c));
    return d;
}
__device__ __forceinline__ unsigned long long fmul2(unsigned long long a,
                                                    unsigned long long b) {
    unsigned long long d;
    asm("mul.rn.f32x2 %0,%1,%2;" : "=l"(d) : "l"(a), "l"(b));
    return d;
}

// ---- kernel 0: detect int64 vs int32 edge_index ----
__global__ void k_detect(const void* ei) {
    if (threadIdx.x == 0) {
        const unsigned long long* p = (const unsigned long long*)ei;
        int ok = 1;
        #pragma unroll
        for (int i = 0; i < 16; i++) {
            if (p[i] >= (unsigned long long)NNODES) ok = 0;
        }
        g_is64 = ok;  // int32 data read as u64 has a nonzero high word w.h.p.
    }
}

// ---- kernel 1: zero the aggregation buffer ----
__global__ void k_zero() {
    int i = blockIdx.x * blockDim.x + threadIdx.x;
    if (i < NNODES * CW) g_aggr[i] = 0.f;
}

// ---- kernel 2: h = lrelu(x @ W_in + b_in), warp = 2 nodes, lane = channel ----
__global__ void k_in(const float* __restrict__ x, const float* __restrict__ Win,
                     const float* __restrict__ bin) {
    __shared__ float Ws[FIN * CW];
    __shared__ float bs[CW];
    for (int i = threadIdx.x; i < FIN * CW; i += blockDim.x) Ws[i] = Win[i];
    if (threadIdx.x < CW) bs[threadIdx.x] = bin[threadIdx.x];
    __syncthreads();

    int gw = (blockIdx.x * blockDim.x + threadIdx.x) >> 5;
    int lane = threadIdx.x & 31;
    int n0 = gw * 2;
    if (n0 >= NNODES) return;
    bool two = (n0 + 1) < NNODES;

    float acc0 = bs[lane], acc1 = bs[lane];
    const float4* x0 = (const float4*)(x + (size_t)n0 * FIN);
    const float4* x1 = (const float4*)(x + (size_t)(two ? n0 + 1 : n0) * FIN);
    #pragma unroll 8
    for (int k4 = 0; k4 < FIN / 4; k4++) {
        float4 a = x0[k4], b = x1[k4];
        float w0 = Ws[(k4 * 4 + 0) * CW + lane];
        float w1 = Ws[(k4 * 4 + 1) * CW + lane];
        float w2 = Ws[(k4 * 4 + 2) * CW + lane];
        float w3 = Ws[(k4 * 4 + 3) * CW + lane];
        acc0 = fmaf(a.x, w0, acc0); acc0 = fmaf(a.y, w1, acc0);
        acc0 = fmaf(a.z, w2, acc0); acc0 = fmaf(a.w, w3, acc0);
        acc1 = fmaf(b.x, w0, acc1); acc1 = fmaf(b.y, w1, acc1);
        acc1 = fmaf(b.z, w2, acc1); acc1 = fmaf(b.w, w3, acc1);
    }
    g_h[n0 * CW + lane] = lrelu(acc0);
    if (two) g_h[(n0 + 1) * CW + lane] = lrelu(acc1);
}

// ---- kernel 3: fused per-edge NNConv message + scatter-add ----
// lane = output channel o; channel-paired f32x2 math; 4 edges per warp-iter.
// 512 threads/CTA, 2 CTA/SM -> 32 warps/SM. W staged as ulonglong2 (LDS.128).
// msg_o = sum_c h[src][c] * lrelu( sum_f ea[f]*W_edge[f][c*32+o] + b_edge[c*32+o] )
__global__ void __launch_bounds__(512) k_edge(const void* __restrict__ eidx,
                                              const float* __restrict__ eattr,
                                              const float* __restrict__ Wedge,
                                              const float* __restrict__ bedge) {
    extern __shared__ __align__(16) unsigned char shraw[];
    // Wq4[(f*8 + c4)*32 + o] : .x = (W[f][(4c4+0)*32+o], W[f][(4c4+1)*32+o])
    //                          .y = (W[f][(4c4+2)*32+o], W[f][(4c4+3)*32+o])
    ulonglong2* Wq4 = (ulonglong2*)shraw;                    // 16*8*32*16B = 64KB
    ulonglong2* bq4 = Wq4 + FE * 8 * 32;                     // 8*32*16B = 4KB
    float* hst = (float*)(bq4 + 8 * 32);                     // WPB*UE*32*4B = 8KB

    for (int p = threadIdx.x; p < FE * 8 * 32; p += blockDim.x) {
        int f = p >> 8; int r = p & 255; int c4 = r >> 5; int o = r & 31;
        const float* wf = Wedge + f * 1024 + (4 * c4) * 32 + o;
        ulonglong2 v;
        v.x = pack2(wf[0], wf[32]);
        v.y = pack2(wf[64], wf[96]);
        Wq4[p] = v;
    }
    for (int p = threadIdx.x; p < 8 * 32; p += blockDim.x) {
        int c4 = p >> 5; int o = p & 31;
        const float* bf = bedge + (4 * c4) * 32 + o;
        ulonglong2 v;
        v.x = pack2(bf[0], bf[32]);
        v.y = pack2(bf[64], bf[96]);
        bq4[p] = v;
    }
    __syncthreads();

    const int lane = threadIdx.x & 31;
    const int warp = threadIdx.x >> 5;
    const long long* e64 = (const long long*)eidx;
    const int* e32 = (const int*)eidx;
    const int is64 = g_is64;
    float* hw = hst + warp * (UE * 32);
    const unsigned long long* hq = (const unsigned long long*)hw;

    const unsigned long long K0505 = pack2(0.505f, 0.505f);
    const unsigned long long K0495 = pack2(0.495f, 0.495f);
    const unsigned long long MABS = 0x7FFFFFFF7FFFFFFFULL;

    const int ngroups = NEDGES / (WPB * UE);  // 64 edges per block-iter
    for (int g = blockIdx.x; g < ngroups; g += gridDim.x) {
        const int ebase = g * (WPB * UE) + warp * UE;
        int dsts[UE];
        unsigned long long ea2[UE][FE];
        #pragma unroll
        for (int u = 0; u < UE; u++) {
            const int e = ebase + u;
            int s, d;
            if (is64) { s = (int)e64[e]; d = (int)e64[NEDGES + e]; }
            else      { s = e32[e];      d = e32[NEDGES + e]; }
            dsts[u] = d;
            hw[u * 32 + lane] = g_h[(size_t)s * CW + lane];  // stage source row
            const float4* ep = (const float4*)(eattr + (size_t)e * FE);
            #pragma unroll
            for (int q = 0; q < 4; q++) {
                float4 v = ep[q];
                ea2[u][q * 4 + 0] = pack2(v.x, v.x);
                ea2[u][q * 4 + 1] = pack2(v.y, v.y);
                ea2[u][q * 4 + 2] = pack2(v.z, v.z);
                ea2[u][q * 4 + 3] = pack2(v.w, v.w);
            }
        }
        __syncwarp();

        unsigned long long msg[UE];
        #pragma unroll
        for (int u = 0; u < UE; u++) msg[u] = 0ULL;

        #pragma unroll 1
        for (int c4 = 0; c4 < 8; c4++) {
            ulonglong2 bb = bq4[c4 * 32 + lane];
            unsigned long long z0[UE], z1[UE];
            #pragma unroll
            for (int u = 0; u < UE; u++) { z0[u] = bb.x; z1[u] = bb.y; }
            #pragma unroll
            for (int f = 0; f < FE; f++) {
                ulonglong2 w = Wq4[(f * 8 + c4) * 32 + lane];
                #pragma unroll
                for (int u = 0; u < UE; u++) {
                    z0[u] = ffma2(ea2[u][f], w.x, z0[u]);
                    z1[u] = ffma2(ea2[u][f], w.y, z1[u]);
                }
            }
            // packed leaky-relu: t = 0.505*z + 0.495*|z|, then msg += h2 * t
            #pragma unroll
            for (int u = 0; u < UE; u++) {
                unsigned long long t0 = ffma2(K0495, z0[u] & MABS, fmul2(K0505, z0[u]));
                msg[u] = ffma2(hq[u * 16 + 2 * c4], t0, msg[u]);
                unsigned long long t1 = ffma2(K0495, z1[u] & MABS, fmul2(K0505, z1[u]));
                msg[u] = ffma2(hq[u * 16 + 2 * c4 + 1], t1, msg[u]);
            }
        }
        #pragma unroll
        for (int u = 0; u < UE; u++) {
            float a, b;
            unpack2(msg[u], a, b);
            atomicAdd(&g_aggr[(size_t)dsts[u] * CW + lane], a + b);
        }
        __syncwarp();  // hw reused next group (cross-lane reads)
    }
}

// ---- kernel 4: out = lrelu(aggr + h@W_root + b_conv) @ W_out + b_out ----
__global__ void k_out(const float* __restrict__ Wr, const float* __restrict__ bc,
                      const float* __restrict__ Wo, const float* __restrict__ bo,
                      float* __restrict__ out) {
    __shared__ float Wrs[CW * CW];
    __shared__ float Wos[CW];
    __shared__ float bcs[CW];
    for (int i = threadIdx.x; i < CW * CW; i += blockDim.x) Wrs[i] = Wr[i];
    if (threadIdx.x < CW) { Wos[threadIdx.x] = Wo[threadIdx.x]; bcs[threadIdx.x] = bc[threadIdx.x]; }
    __syncthreads();

    int gw = (blockIdx.x * blockDim.x + threadIdx.x) >> 5;
    int lane = threadIdx.x & 31;
    if (gw >= NNODES) return;

    float r = g_aggr[(size_t)gw * CW + lane] + bcs[lane];
    const float4* hp = (const float4*)(g_h + (size_t)gw * CW);
    #pragma unroll
    for (int c4 = 0; c4 < CW / 4; c4++) {
        float4 h4 = hp[c4];
        int c = c4 * 4;
        r = fmaf(h4.x, Wrs[(c + 0) * CW + lane], r);
        r = fmaf(h4.y, Wrs[(c + 1) * CW + lane], r);
        r = fmaf(h4.z, Wrs[(c + 2) * CW + lane], r);
        r = fmaf(h4.w, Wrs[(c + 3) * CW + lane], r);
    }
    float t = lrelu(r) * Wos[lane];
    #pragma unroll
    for (int off = 16; off; off >>= 1) t += __shfl_xor_sync(0xFFFFFFFFu, t, off);
    if (lane == 0) out[gw] = t + bo[0];
}

extern "C" void kernel_launch(void* const* d_in, const int* in_sizes, int n_in,
                              void* d_out, int out_size) {
    const float* x     = (const float*)d_in[0];
    const void*  ei    = d_in[1];
    const float* ea    = (const float*)d_in[2];
    const float* Win   = (const float*)d_in[3];
    const float* bin   = (const float*)d_in[4];
    const float* Wedge = (const float*)d_in[5];
    const float* bedge = (const float*)d_in[6];
    const float* Wroot = (const float*)d_in[7];
    const float* bconv = (const float*)d_in[8];
    const float* Wout  = (const float*)d_in[9];
    const float* bout  = (const float*)d_in[10];
    float* out = (float*)d_out;

    const int smem = (FE * 8 * 32 + 8 * 32) * 16 + WPB * UE * 32 * 4;  // 77824 B
    cudaFuncSetAttribute(k_edge, cudaFuncAttributeMaxDynamicSharedMemorySize, smem);

    k_detect<<<1, 32>>>(ei);
    k_zero<<<(NNODES * CW + 255) / 256, 256>>>();
    k_in<<<(((NNODES + 1) / 2) * 32 + 255) / 256, 256>>>(x, Win, bin);
    k_edge<<<296, 512, smem>>>(ei, ea, Wedge, bedge);
    k_out<<<(NNODES * 32 + 255) / 256, 256>>>(Wroot, bconv, Wout, bout, out);
}

// round 10
// speedup vs baseline: 1.6891x; 1.5299x over previous
#include <cuda_runtime.h>
#include <cuda_bf16.h>
#include <cstdint>

#define NNODES 25000
#define NEDGES 400000
#define FIN 128
#define CW 32
#define WPB 16            // warps per block
#define THREADS 512
#define NTILES 25000      // 16-edge tiles

// persistent scratch (no allocs allowed)
__device__ float g_h[NNODES * CW];
__device__ float g_aggr[NNODES * CW];
__device__ int g_is64;

__device__ __forceinline__ float lrelu(float v) {
    return fmaxf(v, 0.f) + 0.01f * fminf(v, 0.f);
}
__device__ __forceinline__ uint32_t bp2(__nv_bfloat16 a, __nv_bfloat16 b) {
    return ((uint32_t)__bfloat16_as_ushort(b) << 16) | __bfloat16_as_ushort(a);
}
__device__ __forceinline__ uint32_t smem_u32(const void* p) {
    uint32_t a;
    asm("{ .reg .u64 t; cvta.to.shared.u64 t,%1; cvt.u32.u64 %0,t; }" : "=r"(a) : "l"(p));
    return a;
}
__device__ __forceinline__ void ldsm4(uint32_t* r, uint32_t addr) {
    asm volatile("ldmatrix.sync.aligned.m8n8.x4.shared.b16 {%0,%1,%2,%3},[%4];"
                 : "=r"(r[0]), "=r"(r[1]), "=r"(r[2]), "=r"(r[3]) : "r"(addr));
}
__device__ __forceinline__ void mma16816(float* d, const uint32_t* a, const uint32_t* b,
                                         float c0, float c1, float c2, float c3) {
    asm volatile("mma.sync.aligned.m16n8k16.row.col.f32.bf16.bf16.f32 "
                 "{%0,%1,%2,%3},{%4,%5,%6,%7},{%8,%9},{%10,%11,%12,%13};"
                 : "=f"(d[0]), "=f"(d[1]), "=f"(d[2]), "=f"(d[3])
                 : "r"(a[0]), "r"(a[1]), "r"(a[2]), "r"(a[3]), "r"(b[0]), "r"(b[1]),
                   "f"(c0), "f"(c1), "f"(c2), "f"(c3));
}

// smem layout (bytes): W' 1024 rows x 128B | A tiles 16w x 2KB | h 16w x 2176B
#define S_W 0
#define S_A 131072
#define S_H 163840
#define S_TOTAL 198656

// ---- kernel 0: detect int64 vs int32 edge_index ----
__global__ void k_detect(const void* ei) {
    if (threadIdx.x == 0) {
        const unsigned long long* p = (const unsigned long long*)ei;
        int ok = 1;
        #pragma unroll
        for (int i = 0; i < 16; i++)
            if (p[i] >= (unsigned long long)NNODES) ok = 0;
        g_is64 = ok;
    }
}
// ---- kernel 1: zero aggr ----
__global__ void k_zero() {
    int i = blockIdx.x * blockDim.x + threadIdx.x;
    if (i < NNODES * CW) g_aggr[i] = 0.f;
}
// ---- kernel 2: h = lrelu(x @ W_in + b_in) ----
__global__ void k_in(const float* __restrict__ x, const float* __restrict__ Win,
                     const float* __restrict__ bin) {
    __shared__ float Ws[FIN * CW];
    __shared__ float bs[CW];
    for (int i = threadIdx.x; i < FIN * CW; i += blockDim.x) Ws[i] = Win[i];
    if (threadIdx.x < CW) bs[threadIdx.x] = bin[threadIdx.x];
    __syncthreads();
    int gw = (blockIdx.x * blockDim.x + threadIdx.x) >> 5;
    int lane = threadIdx.x & 31;
    int n0 = gw * 2;
    if (n0 >= NNODES) return;
    bool two = (n0 + 1) < NNODES;
    float acc0 = bs[lane], acc1 = bs[lane];
    const float4* x0 = (const float4*)(x + (size_t)n0 * FIN);
    const float4* x1 = (const float4*)(x + (size_t)(two ? n0 + 1 : n0) * FIN);
    #pragma unroll 8
    for (int k4 = 0; k4 < FIN / 4; k4++) {
        float4 a = x0[k4], b = x1[k4];
        float w0 = Ws[(k4 * 4 + 0) * CW + lane];
        float w1 = Ws[(k4 * 4 + 1) * CW + lane];
        float w2 = Ws[(k4 * 4 + 2) * CW + lane];
        float w3 = Ws[(k4 * 4 + 3) * CW + lane];
        acc0 = fmaf(a.x, w0, acc0); acc0 = fmaf(a.y, w1, acc0);
        acc0 = fmaf(a.z, w2, acc0); acc0 = fmaf(a.w, w3, acc0);
        acc1 = fmaf(b.x, w0, acc1); acc1 = fmaf(b.y, w1, acc1);
        acc1 = fmaf(b.z, w2, acc1); acc1 = fmaf(b.w, w3, acc1);
    }
    g_h[n0 * CW + lane] = lrelu(acc0);
    if (two) g_h[(n0 + 1) * CW + lane] = lrelu(acc1);
}

// ---- kernel 3: HMMA edge stage ----
// Z[16e,1024n] per warp-tile via mma.m16n8k16 bf16, 3-term split + bias cols:
// A'=[Ah|Al|Ah|1,1,0..](K=64), B' row n=[Wh|Wh|Wl|b_hi,b_lo,0..]. Epilogue fused:
// msg[e][o] += h[src_e][c] * lrelu(Z[e][c*32+o]); scatter-atomics at tile end.
__global__ void __launch_bounds__(THREADS, 1) k_edge(const void* __restrict__ eidx,
                                                     const float* __restrict__ eattr,
                                                     const float* __restrict__ Wedge,
                                                     const float* __restrict__ bedge) {
    extern __shared__ __align__(128) unsigned char sm[];
    const uint32_t smb = smem_u32(sm);
    const int tid = threadIdx.x, lane = tid & 31, warp = tid >> 5;

    // ---- build W' (once per block)
    for (int n = tid; n < 1024; n += THREADS) {
        uint32_t hp8[8], lp8[8];
        #pragma unroll
        for (int q = 0; q < 8; q++) {
            float w0 = Wedge[(2 * q) * 1024 + n];
            float w1 = Wedge[(2 * q + 1) * 1024 + n];
            __nv_bfloat16 h0 = __float2bfloat16(w0);
            __nv_bfloat16 h1 = __float2bfloat16(w1);
            __nv_bfloat16 l0 = __float2bfloat16(w0 - __bfloat162float(h0));
            __nv_bfloat16 l1 = __float2bfloat16(w1 - __bfloat162float(h1));
            hp8[q] = bp2(h0, h1);
            lp8[q] = bp2(l0, l1);
        }
        float bv = bedge[n];
        __nv_bfloat16 bh = __float2bfloat16(bv);
        __nv_bfloat16 bl = __float2bfloat16(bv - __bfloat162float(bh));
        unsigned char* wr = sm + S_W + n * 128;
        const int sx = n & 7;
        uint4 H0 = make_uint4(hp8[0], hp8[1], hp8[2], hp8[3]);
        uint4 H1 = make_uint4(hp8[4], hp8[5], hp8[6], hp8[7]);
        *(uint4*)(wr + ((0 ^ sx) * 16)) = H0;
        *(uint4*)(wr + ((1 ^ sx) * 16)) = H1;
        *(uint4*)(wr + ((2 ^ sx) * 16)) = H0;
        *(uint4*)(wr + ((3 ^ sx) * 16)) = H1;
        *(uint4*)(wr + ((4 ^ sx) * 16)) = make_uint4(lp8[0], lp8[1], lp8[2], lp8[3]);
        *(uint4*)(wr + ((5 ^ sx) * 16)) = make_uint4(lp8[4], lp8[5], lp8[6], lp8[7]);
        *(uint4*)(wr + ((6 ^ sx) * 16)) = make_uint4(bp2(bh, bl), 0u, 0u, 0u);
        *(uint4*)(wr + ((7 ^ sx) * 16)) = make_uint4(0u, 0u, 0u, 0u);
    }
    __syncthreads();

    const int q4 = lane & 3, grp = lane >> 2;
    const uint32_t Aslot = smb + S_A + warp * 2048;
    // B ldsm addresses (per-thread constants; chunk advance = +1024B)
    uint32_t ba0 = smb + S_W + (lane & 7) * 128 + (((lane >> 3) ^ (lane & 7)) * 16);
    uint32_t bb0 = smb + S_W + (lane & 7) * 128 + ((((lane >> 3) + 4) ^ (lane & 7)) * 16);
    // A ldsm addresses per k-step
    const int arow = (lane & 7) + 8 * ((lane >> 3) & 1);
    uint32_t aaddr[3];
    #pragma unroll
    for (int s = 0; s < 3; s++) {
        int u = 2 * s + (lane >> 4);
        aaddr[s] = Aslot + arow * 128 + ((u ^ (arow & 7)) * 16);
    }
    const uint32_t aFc0 = (q4 == 0) ? 0x3F803F80u : 0u;  // bias A frag (1,1)
    uint32_t acf[4];
    acf[0] = aFc0; acf[1] = aFc0; acf[2] = 0u; acf[3] = 0u;
    float* hsl = (float*)(sm + S_H + warp * 2176);  // 16 edges x 34 floats

    const long long* e64 = (const long long*)eidx;
    const int* e32 = (const int*)eidx;
    const int is64 = g_is64;

    for (int tile = blockIdx.x * WPB + warp; tile < NTILES; tile += gridDim.x * WPB) {
        const int ebase = tile * 16;
        // lanes 0-15: src[e]; lanes 16-31: dst[e]
        int v;
        {
            int idx = (lane >> 4) * NEDGES + ebase + (lane & 15);
            v = is64 ? (int)e64[idx] : e32[idx];
        }
        // ---- stage A tile (16x64 bf16, swizzled) + h rows; thread = half edge
        {
            const int e = lane >> 1, hf = lane & 1;
            const int se = __shfl_sync(0xFFFFFFFFu, v, e);
            const float4* ep = (const float4*)(eattr + (size_t)(ebase + e) * 16) + hf * 2;
            float4 x0 = ep[0], x1 = ep[1];
            float f[8] = {x0.x, x0.y, x0.z, x0.w, x1.x, x1.y, x1.z, x1.w};
            uint32_t hp[4], lp[4];
            #pragma unroll
            for (int j = 0; j < 4; j++) {
                __nv_bfloat16 h0 = __float2bfloat16(f[2 * j]);
                __nv_bfloat16 h1 = __float2bfloat16(f[2 * j + 1]);
                __nv_bfloat16 l0 = __float2bfloat16(f[2 * j] - __bfloat162float(h0));
                __nv_bfloat16 l1 = __float2bfloat16(f[2 * j + 1] - __bfloat162float(h1));
                hp[j] = bp2(h0, h1);
                lp[j] = bp2(l0, l1);
            }
            unsigned char* ab = sm + S_A + warp * 2048 + e * 128;
            const int sx = e & 7;
            uint4 HV = make_uint4(hp[0], hp[1], hp[2], hp[3]);
            *(uint4*)(ab + (((0 + hf) ^ sx) * 16)) = HV;
            *(uint4*)(ab + (((2 + hf) ^ sx) * 16)) = make_uint4(lp[0], lp[1], lp[2], lp[3]);
            *(uint4*)(ab + (((4 + hf) ^ sx) * 16)) = HV;
            *(uint4*)(ab + (((6 + hf) ^ sx) * 16)) =
                hf ? make_uint4(0u, 0u, 0u, 0u) : make_uint4(0x3F803F80u, 0u, 0u, 0u);
            // stage FULL 16 floats of this half of the h row (8 x float2)
            const float2* hp2 = (const float2*)(g_h + (size_t)se * CW + hf * 16);
            float2* hd = (float2*)(hsl + e * 34 + hf * 16);
            #pragma unroll
            for (int j = 0; j < 8; j++) hd[j] = hp2[j];
        }
        const int d0 = __shfl_sync(0xFFFFFFFFu, v, 16 + grp);
        const int d1 = __shfl_sync(0xFFFFFFFFu, v, 24 + grp);
        __syncwarp();

        uint32_t aF0[4], aF1[4], aF2[4];
        ldsm4(aF0, aaddr[0]);
        ldsm4(aF1, aaddr[1]);
        ldsm4(aF2, aaddr[2]);

        float msg[16];
        #pragma unroll
        for (int i = 0; i < 16; i++) msg[i] = 0.f;

        uint32_t ba = ba0, bb = bb0;
        float h0 = 0.f, h1 = 0.f;
        #pragma unroll 4
        for (int chunk = 0; chunk < 128; chunk++) {
            if ((chunk & 3) == 0) {
                const int c = chunk >> 2;
                h0 = hsl[grp * 34 + c];
                h1 = hsl[(grp + 8) * 34 + c];
            }
            uint32_t B0[4], B1[4];
            ldsm4(B0, ba); ldsm4(B1, bb);
            ba += 1024; bb += 1024;
            float d[4];
            mma16816(d, aF0, B0 + 0, 0.f, 0.f, 0.f, 0.f);
            mma16816(d, aF1, B0 + 2, d[0], d[1], d[2], d[3]);
            mma16816(d, aF2, B1 + 0, d[0], d[1], d[2], d[3]);
            mma16816(d, acf, B1 + 2, d[0], d[1], d[2], d[3]);
            const int p = chunk & 3;
            float t0 = fmaf(0.495f, fabsf(d[0]), 0.505f * d[0]);
            float t1 = fmaf(0.495f, fabsf(d[1]), 0.505f * d[1]);
            float t2 = fmaf(0.495f, fabsf(d[2]), 0.505f * d[2]);
            float t3 = fmaf(0.495f, fabsf(d[3]), 0.505f * d[3]);
            msg[p * 2 + 0] = fmaf(h0, t0, msg[p * 2 + 0]);
            msg[p * 2 + 1] = fmaf(h0, t1, msg[p * 2 + 1]);
            msg[8 + p * 2 + 0] = fmaf(h1, t2, msg[8 + p * 2 + 0]);
            msg[8 + p * 2 + 1] = fmaf(h1, t3, msg[8 + p * 2 + 1]);
        }
        float* a0p = g_aggr + (size_t)d0 * CW;
        float* a1p = g_aggr + (size_t)d1 * CW;
        #pragma unroll
        for (int p = 0; p < 4; p++) {
            const int o = p * 8 + 2 * q4;
            atomicAdd(a0p + o, msg[p * 2]);
            atomicAdd(a0p + o + 1, msg[p * 2 + 1]);
            atomicAdd(a1p + o, msg[8 + p * 2]);
            atomicAdd(a1p + o + 1, msg[8 + p * 2 + 1]);
        }
        __syncwarp();  // A/h slots reused next tile
    }
}

// ---- kernel 4: out = lrelu(aggr + h@W_root + b_conv) @ W_out + b_out ----
__global__ void k_out(const float* __restrict__ Wr, const float* __restrict__ bc,
                      const float* __restrict__ Wo, const float* __restrict__ bo,
                      float* __restrict__ out) {
    __shared__ float Wrs[CW * CW];
    __shared__ float Wos[CW];
    __shared__ float bcs[CW];
    for (int i = threadIdx.x; i < CW * CW; i += blockDim.x) Wrs[i] = Wr[i];
    if (threadIdx.x < CW) { Wos[threadIdx.x] = Wo[threadIdx.x]; bcs[threadIdx.x] = bc[threadIdx.x]; }
    __syncthreads();
    int gw = (blockIdx.x * blockDim.x + threadIdx.x) >> 5;
    int lane = threadIdx.x & 31;
    if (gw >= NNODES) return;
    float r = g_aggr[(size_t)gw * CW + lane] + bcs[lane];
    const float4* hp = (const float4*)(g_h + (size_t)gw * CW);
    #pragma unroll
    for (int c4 = 0; c4 < CW / 4; c4++) {
        float4 h4 = hp[c4];
        int c = c4 * 4;
        r = fmaf(h4.x, Wrs[(c + 0) * CW + lane], r);
        r = fmaf(h4.y, Wrs[(c + 1) * CW + lane], r);
        r = fmaf(h4.z, Wrs[(c + 2) * CW + lane], r);
        r = fmaf(h4.w, Wrs[(c + 3) * CW + lane], r);
    }
    float t = lrelu(r) * Wos[lane];
    #pragma unroll
    for (int off = 16; off; off >>= 1) t += __shfl_xor_sync(0xFFFFFFFFu, t, off);
    if (lane == 0) out[gw] = t + bo[0];
}

extern "C" void kernel_launch(void* const* d_in, const int* in_sizes, int n_in,
                              void* d_out, int out_size) {
    const float* x     = (const float*)d_in[0];
    const void*  ei    = d_in[1];
    const float* ea    = (const float*)d_in[2];
    const float* Win   = (const float*)d_in[3];
    const float* bin   = (const float*)d_in[4];
    const float* Wedge = (const float*)d_in[5];
    const float* bedge = (const float*)d_in[6];
    const float* Wroot = (const float*)d_in[7];
    const float* bconv = (const float*)d_in[8];
    const float* Wout  = (const float*)d_in[9];
    const float* bout  = (const float*)d_in[10];
    float* out = (float*)d_out;

    cudaFuncSetAttribute(k_edge, cudaFuncAttributeMaxDynamicSharedMemorySize, S_TOTAL);

    k_detect<<<1, 32>>>(ei);
    k_zero<<<(NNODES * CW + 255) / 256, 256>>>();
    k_in<<<(((NNODES + 1) / 2) * 32 + 255) / 256, 256>>>(x, Win, bin);
    k_edge<<<148, THREADS, S_TOTAL>>>(ei, ea, Wedge, bedge);
    k_out<<<(NNODES * 32 + 255) / 256, 256>>>(Wroot, bconv, Wout, bout, out);
}

// round 13
// speedup vs baseline: 1.9904x; 1.1784x over previous
#include <cuda_runtime.h>
#include <cuda_bf16.h>
#include <cstdint>

#define NNODES 25000
#define NEDGES 400000
#define FIN 128
#define CW 32
#define WPB 20            // warps per block
#define THREADS 640
#define NTILES 25000      // 16-edge tiles

// persistent scratch (no allocs allowed)
__device__ float g_h[NNODES * CW];
__device__ float g_aggr[NNODES * CW];
__device__ int g_is64;

__device__ __forceinline__ float lrelu(float v) {
    return fmaxf(v, 0.f) + 0.01f * fminf(v, 0.f);
}
__device__ __forceinline__ uint32_t bp2(__nv_bfloat16 a, __nv_bfloat16 b) {
    return ((uint32_t)__bfloat16_as_ushort(b) << 16) | __bfloat16_as_ushort(a);
}
__device__ __forceinline__ uint32_t smem_u32(const void* p) {
    uint32_t a;
    asm("{ .reg .u64 t; cvta.to.shared.u64 t,%1; cvt.u32.u64 %0,t; }" : "=r"(a) : "l"(p));
    return a;
}
__device__ __forceinline__ void ldsm4(uint32_t* r, uint32_t addr) {
    asm volatile("ldmatrix.sync.aligned.m8n8.x4.shared.b16 {%0,%1,%2,%3},[%4];"
                 : "=r"(r[0]), "=r"(r[1]), "=r"(r[2]), "=r"(r[3]) : "r"(addr));
}
__device__ __forceinline__ void mma16816(float* d, const uint32_t* a, const uint32_t* b,
                                         float c0, float c1, float c2, float c3) {
    asm volatile("mma.sync.aligned.m16n8k16.row.col.f32.bf16.bf16.f32 "
                 "{%0,%1,%2,%3},{%4,%5,%6,%7},{%8,%9},{%10,%11,%12,%13};"
                 : "=f"(d[0]), "=f"(d[1]), "=f"(d[2]), "=f"(d[3])
                 : "r"(a[0]), "r"(a[1]), "r"(a[2]), "r"(a[3]), "r"(b[0]), "r"(b[1]),
                   "f"(c0), "f"(c1), "f"(c2), "f"(c3));
}

// smem layout (bytes)
#define S_W 0                        // W' 1024 rows x 64B ([Wh|Wl]) = 65536
#define S_B 65536                    // bias f32[1024] = 4096
#define S_A 69632                    // A tiles: WPB x 1024B
#define S_H (69632 + WPB * 1024)     // h rows: WPB x 16 x 34 floats (stride 34 -> 8B aligned)
#define S_TOTAL (S_H + WPB * 2176)

// ---- kernel 1: h = lrelu(x @ W_in + b_in); also zeros g_aggr, detects idx dtype ----
__global__ void k_in(const void* __restrict__ ei, const float* __restrict__ x,
                     const float* __restrict__ Win, const float* __restrict__ bin) {
    if (blockIdx.x == 0 && threadIdx.x == 0) {
        const unsigned long long* p = (const unsigned long long*)ei;
        int ok = 1;
        #pragma unroll
        for (int i = 0; i < 16; i++)
            if (p[i] >= (unsigned long long)NNODES) ok = 0;
        g_is64 = ok;  // int32 read as u64 has nonzero high word w.h.p.
    }
    __shared__ float Ws[FIN * CW];
    __shared__ float bs[CW];
    for (int i = threadIdx.x; i < FIN * CW; i += blockDim.x) Ws[i] = Win[i];
    if (threadIdx.x < CW) bs[threadIdx.x] = bin[threadIdx.x];
    __syncthreads();
    int gw = (blockIdx.x * blockDim.x + threadIdx.x) >> 5;
    int lane = threadIdx.x & 31;
    int n0 = gw * 2;
    if (n0 >= NNODES) return;
    bool two = (n0 + 1) < NNODES;
    float acc0 = bs[lane], acc1 = bs[lane];
    const float4* x0 = (const float4*)(x + (size_t)n0 * FIN);
    const float4* x1 = (const float4*)(x + (size_t)(two ? n0 + 1 : n0) * FIN);
    #pragma unroll 8
    for (int k4 = 0; k4 < FIN / 4; k4++) {
        float4 a = x0[k4], b = x1[k4];
        float w0 = Ws[(k4 * 4 + 0) * CW + lane];
        float w1 = Ws[(k4 * 4 + 1) * CW + lane];
        float w2 = Ws[(k4 * 4 + 2) * CW + lane];
        float w3 = Ws[(k4 * 4 + 3) * CW + lane];
        acc0 = fmaf(a.x, w0, acc0); acc0 = fmaf(a.y, w1, acc0);
        acc0 = fmaf(a.z, w2, acc0); acc0 = fmaf(a.w, w3, acc0);
        acc1 = fmaf(b.x, w0, acc1); acc1 = fmaf(b.y, w1, acc1);
        acc1 = fmaf(b.z, w2, acc1); acc1 = fmaf(b.w, w3, acc1);
    }
    g_h[n0 * CW + lane] = lrelu(acc0);
    g_aggr[n0 * CW + lane] = 0.f;
    if (two) {
        g_h[(n0 + 1) * CW + lane] = lrelu(acc1);
        g_aggr[(n0 + 1) * CW + lane] = 0.f;
    }
}

// ---- kernel 2: HMMA edge stage ----
// Z[16e,1024n] per warp-tile, 3 MMAs per 8n-chunk: d = Ah*Wh + C(bias_f32);
// d += Al*Wh (B-frag reuse); d += Ah*Wl. W' row n = [Wh(32B)|Wl(32B)], swizzled
// pos(u,n) = u ^ ((n>>1)&3). Epilogue fused: msg[e][o] += h[src][c]*lrelu(z).
__global__ void __launch_bounds__(THREADS, 1) k_edge(const void* __restrict__ eidx,
                                                     const float* __restrict__ eattr,
                                                     const float* __restrict__ Wedge,
                                                     const float* __restrict__ bedge) {
    extern __shared__ __align__(128) unsigned char sm[];
    const uint32_t smb = smem_u32(sm);
    const int tid = threadIdx.x, lane = tid & 31, warp = tid >> 5;

    // ---- build W' + bias (once per block)
    for (int n = tid; n < 1024; n += THREADS) {
        uint32_t hp8[8], lp8[8];
        #pragma unroll
        for (int q = 0; q < 8; q++) {
            float w0 = Wedge[(2 * q) * 1024 + n];
            float w1 = Wedge[(2 * q + 1) * 1024 + n];
            __nv_bfloat16 h0 = __float2bfloat16(w0);
            __nv_bfloat16 h1 = __float2bfloat16(w1);
            __nv_bfloat16 l0 = __float2bfloat16(w0 - __bfloat162float(h0));
            __nv_bfloat16 l1 = __float2bfloat16(w1 - __bfloat162float(h1));
            hp8[q] = bp2(h0, h1);
            lp8[q] = bp2(l0, l1);
        }
        unsigned char* wr = sm + S_W + n * 64;
        const int sx = (n >> 1) & 3;
        *(uint4*)(wr + ((0 ^ sx) * 16)) = make_uint4(hp8[0], hp8[1], hp8[2], hp8[3]);
        *(uint4*)(wr + ((1 ^ sx) * 16)) = make_uint4(hp8[4], hp8[5], hp8[6], hp8[7]);
        *(uint4*)(wr + ((2 ^ sx) * 16)) = make_uint4(lp8[0], lp8[1], lp8[2], lp8[3]);
        *(uint4*)(wr + ((3 ^ sx) * 16)) = make_uint4(lp8[4], lp8[5], lp8[6], lp8[7]);
        ((float*)(sm + S_B))[n] = bedge[n];
    }
    __syncthreads();

    const int q4 = lane & 3, grp = lane >> 2;
    const uint32_t Aslot = smb + S_A + warp * 1024;
    // B ldsm base (one x4 per chunk: matrices u=0..3 -> [Wh k0-7, Wh k8-15, Wl k0-7, Wl k8-15])
    const int br = lane & 7, bu = lane >> 3;
    const uint32_t bB0 = smb + S_W + br * 64 + ((bu ^ ((br >> 1) & 3)) * 16);
    // A ldsm addresses (aFh: u=0,1 ; aFl: u=2,3)
    const int arow = (lane & 7) + 8 * ((lane >> 3) & 1);
    const int au = lane >> 4, asx = (arow >> 1) & 3;
    const uint32_t aaddrh = Aslot + arow * 64 + (((0 + au) ^ asx) * 16);
    const uint32_t aaddrl = Aslot + arow * 64 + (((2 + au) ^ asx) * 16);
    const float* bias = (const float*)(sm + S_B);
    float* hsl = (float*)(sm + S_H + warp * 2176);  // 16 edges x 34 floats

    const long long* e64 = (const long long*)eidx;
    const int* e32 = (const int*)eidx;
    const int is64 = g_is64;

    for (int tile = blockIdx.x * WPB + warp; tile < NTILES; tile += gridDim.x * WPB) {
        const int ebase = tile * 16;
        // lanes 0-15: src[e]; lanes 16-31: dst[e]
        int v;
        {
            int idx = (lane >> 4) * NEDGES + ebase + (lane & 15);
            v = is64 ? (int)e64[idx] : e32[idx];
        }
        // ---- stage A tile (16 x [Ah(32B)|Al(32B)], swizzled) + h rows; thread = half edge
        {
            const int e = lane >> 1, hf = lane & 1;
            const int se = __shfl_sync(0xFFFFFFFFu, v, e);
            const float4* ep = (const float4*)(eattr + (size_t)(ebase + e) * 16) + hf * 2;
            float4 x0 = ep[0], x1 = ep[1];
            float f[8] = {x0.x, x0.y, x0.z, x0.w, x1.x, x1.y, x1.z, x1.w};
            uint32_t hp[4], lp[4];
            #pragma unroll
            for (int j = 0; j < 4; j++) {
                __nv_bfloat16 h0 = __float2bfloat16(f[2 * j]);
                __nv_bfloat16 h1 = __float2bfloat16(f[2 * j + 1]);
                __nv_bfloat16 l0 = __float2bfloat16(f[2 * j] - __bfloat162float(h0));
                __nv_bfloat16 l1 = __float2bfloat16(f[2 * j + 1] - __bfloat162float(h1));
                hp[j] = bp2(h0, h1);
                lp[j] = bp2(l0, l1);
            }
            unsigned char* ab = sm + S_A + warp * 1024 + e * 64;
            const int sx = (e >> 1) & 3;
            // hi half of features -> chunk u=hf; lo half -> chunk u=2+hf
            *(uint4*)(ab + ((hf ^ sx) * 16)) = make_uint4(hp[0], hp[1], hp[2], hp[3]);
            *(uint4*)(ab + (((2 + hf) ^ sx) * 16)) = make_uint4(lp[0], lp[1], lp[2], lp[3]);
            // stage full 16 floats of this half of the h row (stride 34 -> 8B aligned)
            const float2* hp2 = (const float2*)(g_h + (size_t)se * CW + hf * 16);
            float2* hd = (float2*)(hsl + e * 34 + hf * 16);
            #pragma unroll
            for (int j = 0; j < 8; j++) hd[j] = hp2[j];
        }
        const int d0 = __shfl_sync(0xFFFFFFFFu, v, 16 + grp);
        const int d1 = __shfl_sync(0xFFFFFFFFu, v, 24 + grp);
        __syncwarp();

        uint32_t aFh[4], aFl[4];
        ldsm4(aFh, aaddrh);
        ldsm4(aFl, aaddrl);

        float msg[16];
        #pragma unroll
        for (int i = 0; i < 16; i++) msg[i] = 0.f;

        uint32_t bB = bB0;
        const float* bp = bias + 2 * q4;
        float h0 = 0.f, h1 = 0.f;
        #pragma unroll 4
        for (int chunk = 0; chunk < 128; chunk++) {
            if ((chunk & 3) == 0) {
                const int c = chunk >> 2;
                h0 = hsl[grp * 34 + c];
                h1 = hsl[(grp + 8) * 34 + c];
            }
            uint32_t B0[4];
            ldsm4(B0, bB);
            bB += 512;
            float2 bv = *(const float2*)bp;
            bp += 8;
            float d[4];
            mma16816(d, aFh, B0 + 0, bv.x, bv.y, bv.x, bv.y);   // Ah*Wh + bias
            mma16816(d, aFl, B0 + 0, d[0], d[1], d[2], d[3]);   // + Al*Wh
            mma16816(d, aFh, B0 + 2, d[0], d[1], d[2], d[3]);   // + Ah*Wl
            const int p = chunk & 3;
            float t0 = fmaf(0.495f, fabsf(d[0]), 0.505f * d[0]);
            float t1 = fmaf(0.495f, fabsf(d[1]), 0.505f * d[1]);
            float t2 = fmaf(0.495f, fabsf(d[2]), 0.505f * d[2]);
            float t3 = fmaf(0.495f, fabsf(d[3]), 0.505f * d[3]);
            msg[p * 2 + 0] = fmaf(h0, t0, msg[p * 2 + 0]);
            msg[p * 2 + 1] = fmaf(h0, t1, msg[p * 2 + 1]);
            msg[8 + p * 2 + 0] = fmaf(h1, t2, msg[8 + p * 2 + 0]);
            msg[8 + p * 2 + 1] = fmaf(h1, t3, msg[8 + p * 2 + 1]);
        }
        float* a0p = g_aggr + (size_t)d0 * CW;
        float* a1p = g_aggr + (size_t)d1 * CW;
        #pragma unroll
        for (int p = 0; p < 4; p++) {
            const int o = p * 8 + 2 * q4;
            atomicAdd(a0p + o, msg[p * 2]);
            atomicAdd(a0p + o + 1, msg[p * 2 + 1]);
            atomicAdd(a1p + o, msg[8 + p * 2]);
            atomicAdd(a1p + o + 1, msg[8 + p * 2 + 1]);
        }
        __syncwarp();  // A/h slots reused next tile
    }
}

// ---- kernel 3: out = lrelu(aggr + h@W_root + b_conv) @ W_out + b_out ----
__global__ void k_out(const float* __restrict__ Wr, const float* __restrict__ bc,
                      const float* __restrict__ Wo, const float* __restrict__ bo,
                      float* __restrict__ out) {
    __shared__ float Wrs[CW * CW];
    __shared__ float Wos[CW];
    __shared__ float bcs[CW];
    for (int i = threadIdx.x; i < CW * CW; i += blockDim.x) Wrs[i] = Wr[i];
    if (threadIdx.x < CW) { Wos[threadIdx.x] = Wo[threadIdx.x]; bcs[threadIdx.x] = bc[threadIdx.x]; }
    __syncthreads();
    int gw = (blockIdx.x * blockDim.x + threadIdx.x) >> 5;
    int lane = threadIdx.x & 31;
    if (gw >= NNODES) return;
    float r = g_aggr[(size_t)gw * CW + lane] + bcs[lane];
    const float4* hp = (const float4*)(g_h + (size_t)gw * CW);
    #pragma unroll
    for (int c4 = 0; c4 < CW / 4; c4++) {
        float4 h4 = hp[c4];
        int c = c4 * 4;
        r = fmaf(h4.x, Wrs[(c + 0) * CW + lane], r);
        r = fmaf(h4.y, Wrs[(c + 1) * CW + lane], r);
        r = fmaf(h4.z, Wrs[(c + 2) * CW + lane], r);
        r = fmaf(h4.w, Wrs[(c + 3) * CW + lane], r);
    }
    float t = lrelu(r) * Wos[lane];
    #pragma unroll
    for (int off = 16; off; off >>= 1) t += __shfl_xor_sync(0xFFFFFFFFu, t, off);
    if (lane == 0) out[gw] = t + bo[0];
}

extern "C" void kernel_launch(void* const* d_in, const int* in_sizes, int n_in,
                              void* d_out, int out_size) {
    const float* x     = (const float*)d_in[0];
    const void*  ei    = d_in[1];
    const float* ea    = (const float*)d_in[2];
    const float* Win   = (const float*)d_in[3];
    const float* bin   = (const float*)d_in[4];
    const float* Wedge = (const float*)d_in[5];
    const float* bedge = (const float*)d_in[6];
    const float* Wroot = (const float*)d_in[7];
    const float* bconv = (const float*)d_in[8];
    const float* Wout  = (const float*)d_in[9];
    const float* bout  = (const float*)d_in[10];
    float* out = (float*)d_out;

    cudaFuncSetAttribute(k_edge, cudaFuncAttributeMaxDynamicSharedMemorySize, S_TOTAL);

    k_in<<<(((NNODES + 1) / 2) * 32 + 255) / 256, 256>>>(ei, x, Win, bin);
    k_edge<<<148, THREADS, S_TOTAL>>>(ei, ea, Wedge, bedge);
    k_out<<<(NNODES * 32 + 255) / 256, 256>>>(Wroot, bconv, Wout, bout, out);
}

// round 14
// speedup vs baseline: 2.0744x; 1.0422x over previous
#include <cuda_runtime.h>
#include <cuda_bf16.h>
#include <cstdint>

#define NNODES 25000
#define NEDGES 400000
#define FIN 128
#define CW 32
#define WPB 16            // warps per block
#define THREADS 512
#define NTILES 12500      // 32-edge tiles

// persistent scratch (no allocs allowed)
__device__ float g_h[NNODES * CW];
__device__ float g_aggr[NNODES * CW];
__device__ int g_is64;

__device__ __forceinline__ float lrelu(float v) {
    return fmaxf(v, 0.f) + 0.01f * fminf(v, 0.f);
}
__device__ __forceinline__ uint32_t bp2(__nv_bfloat16 a, __nv_bfloat16 b) {
    return ((uint32_t)__bfloat16_as_ushort(b) << 16) | __bfloat16_as_ushort(a);
}
__device__ __forceinline__ uint32_t smem_u32(const void* p) {
    uint32_t a;
    asm("{ .reg .u64 t; cvta.to.shared.u64 t,%1; cvt.u32.u64 %0,t; }" : "=r"(a) : "l"(p));
    return a;
}
__device__ __forceinline__ void ldsm4(uint32_t* r, uint32_t addr) {
    asm volatile("ldmatrix.sync.aligned.m8n8.x4.shared.b16 {%0,%1,%2,%3},[%4];"
                 : "=r"(r[0]), "=r"(r[1]), "=r"(r[2]), "=r"(r[3]) : "r"(addr));
}
__device__ __forceinline__ void mma16816(float* d, const uint32_t* a, const uint32_t* b,
                                         float c0, float c1, float c2, float c3) {
    asm volatile("mma.sync.aligned.m16n8k16.row.col.f32.bf16.bf16.f32 "
                 "{%0,%1,%2,%3},{%4,%5,%6,%7},{%8,%9},{%10,%11,%12,%13};"
                 : "=f"(d[0]), "=f"(d[1]), "=f"(d[2]), "=f"(d[3])
                 : "r"(a[0]), "r"(a[1]), "r"(a[2]), "r"(a[3]), "r"(b[0]), "r"(b[1]),
                   "f"(c0), "f"(c1), "f"(c2), "f"(c3));
}

// smem layout (bytes)
#define S_W 0                        // W' 1024 rows x 64B ([Wh|Wl]) = 65536
#define S_B 65536                    // bias f32[1024] = 4096
#define S_A 69632                    // A tiles: WPB x 2048B (32 edges x 64B)
#define S_H (S_A + WPB * 2048)       // h rows: WPB x 32 x 36 floats (stride 36 -> 16B aligned)
#define S_TOTAL (S_H + WPB * 4608)

// ---- kernel 1: h = lrelu(x @ W_in + b_in); zeros g_aggr; detects idx dtype ----
// warp = 4 nodes (25000 = 4*6250 exactly), lane = channel
__global__ void k_in(const void* __restrict__ ei, const float* __restrict__ x,
                     const float* __restrict__ Win, const float* __restrict__ bin) {
    if (blockIdx.x == 0 && threadIdx.x == 0) {
        const unsigned long long* p = (const unsigned long long*)ei;
        int ok = 1;
        #pragma unroll
        for (int i = 0; i < 16; i++)
            if (p[i] >= (unsigned long long)NNODES) ok = 0;
        g_is64 = ok;  // int32 read as u64 has nonzero high word w.h.p.
    }
    __shared__ float Ws[FIN * CW];
    __shared__ float bs[CW];
    for (int i = threadIdx.x; i < FIN * CW; i += blockDim.x) Ws[i] = Win[i];
    if (threadIdx.x < CW) bs[threadIdx.x] = bin[threadIdx.x];
    __syncthreads();
    int gw = (blockIdx.x * blockDim.x + threadIdx.x) >> 5;
    int lane = threadIdx.x & 31;
    if (gw >= NNODES / 4) return;
    int n0 = gw * 4;
    float acc0 = bs[lane], acc1 = acc0, acc2 = acc0, acc3 = acc0;
    const float4* x0 = (const float4*)(x + (size_t)n0 * FIN);
    const float4* x1 = (const float4*)(x + (size_t)(n0 + 1) * FIN);
    const float4* x2 = (const float4*)(x + (size_t)(n0 + 2) * FIN);
    const float4* x3 = (const float4*)(x + (size_t)(n0 + 3) * FIN);
    #pragma unroll 4
    for (int k4 = 0; k4 < FIN / 4; k4++) {
        float4 a = x0[k4], b = x1[k4], c = x2[k4], d = x3[k4];
        float w0 = Ws[(k4 * 4 + 0) * CW + lane];
        float w1 = Ws[(k4 * 4 + 1) * CW + lane];
        float w2 = Ws[(k4 * 4 + 2) * CW + lane];
        float w3 = Ws[(k4 * 4 + 3) * CW + lane];
        acc0 = fmaf(a.x, w0, acc0); acc0 = fmaf(a.y, w1, acc0);
        acc0 = fmaf(a.z, w2, acc0); acc0 = fmaf(a.w, w3, acc0);
        acc1 = fmaf(b.x, w0, acc1); acc1 = fmaf(b.y, w1, acc1);
        acc1 = fmaf(b.z, w2, acc1); acc1 = fmaf(b.w, w3, acc1);
        acc2 = fmaf(c.x, w0, acc2); acc2 = fmaf(c.y, w1, acc2);
        acc2 = fmaf(c.z, w2, acc2); acc2 = fmaf(c.w, w3, acc2);
        acc3 = fmaf(d.x, w0, acc3); acc3 = fmaf(d.y, w1, acc3);
        acc3 = fmaf(d.z, w2, acc3); acc3 = fmaf(d.w, w3, acc3);
    }
    g_h[(n0 + 0) * CW + lane] = lrelu(acc0);
    g_h[(n0 + 1) * CW + lane] = lrelu(acc1);
    g_h[(n0 + 2) * CW + lane] = lrelu(acc2);
    g_h[(n0 + 3) * CW + lane] = lrelu(acc3);
    g_aggr[(n0 + 0) * CW + lane] = 0.f;
    g_aggr[(n0 + 1) * CW + lane] = 0.f;
    g_aggr[(n0 + 2) * CW + lane] = 0.f;
    g_aggr[(n0 + 3) * CW + lane] = 0.f;
}

// ---- kernel 2: HMMA edge stage, 32 edges per warp-tile ----
// Per 8n-chunk: 1 ldsm.x4 B [Wh|Wl] + 1 bias LDS.64 feed 6 MMAs (2 independent
// 3-chains, tiles rows 0-15 / 16-31): d = Ah*Wh + bias; d += Al*Wh; d += Ah*Wl.
// Epilogue: msg += (0.505h)*d + (0.495h)*|d|. Scatter-atomics at tile end.
__global__ void __launch_bounds__(THREADS, 1) k_edge(const void* __restrict__ eidx,
                                                     const float* __restrict__ eattr,
                                                     const float* __restrict__ Wedge,
                                                     const float* __restrict__ bedge) {
    extern __shared__ __align__(128) unsigned char sm[];
    const uint32_t smb = smem_u32(sm);
    const int tid = threadIdx.x, lane = tid & 31, warp = tid >> 5;

    // ---- build W' + bias (once per block)
    for (int n = tid; n < 1024; n += THREADS) {
        uint32_t hp8[8], lp8[8];
        #pragma unroll
        for (int q = 0; q < 8; q++) {
            float w0 = Wedge[(2 * q) * 1024 + n];
            float w1 = Wedge[(2 * q + 1) * 1024 + n];
            __nv_bfloat16 h0 = __float2bfloat16(w0);
            __nv_bfloat16 h1 = __float2bfloat16(w1);
            __nv_bfloat16 l0 = __float2bfloat16(w0 - __bfloat162float(h0));
            __nv_bfloat16 l1 = __float2bfloat16(w1 - __bfloat162float(h1));
            hp8[q] = bp2(h0, h1);
            lp8[q] = bp2(l0, l1);
        }
        unsigned char* wr = sm + S_W + n * 64;
        const int sx = (n >> 1) & 3;
        *(uint4*)(wr + ((0 ^ sx) * 16)) = make_uint4(hp8[0], hp8[1], hp8[2], hp8[3]);
        *(uint4*)(wr + ((1 ^ sx) * 16)) = make_uint4(hp8[4], hp8[5], hp8[6], hp8[7]);
        *(uint4*)(wr + ((2 ^ sx) * 16)) = make_uint4(lp8[0], lp8[1], lp8[2], lp8[3]);
        *(uint4*)(wr + ((3 ^ sx) * 16)) = make_uint4(lp8[4], lp8[5], lp8[6], lp8[7]);
        ((float*)(sm + S_B))[n] = bedge[n];
    }
    __syncthreads();

    const int q4 = lane & 3, grp = lane >> 2;
    const uint32_t Aslot = smb + S_A + warp * 2048;
    // B ldsm base (one x4 per chunk: u=0..3 -> [Wh k0-7, Wh k8-15, Wl k0-7, Wl k8-15])
    const int br = lane & 7, bu = lane >> 3;
    const uint32_t bB0 = smb + S_W + br * 64 + ((bu ^ ((br >> 1) & 3)) * 16);
    // A ldsm addresses: tile0 rows 0-15 at Aslot, tile1 rows 16-31 at +1024
    const int arow = (lane & 7) + 8 * ((lane >> 3) & 1);
    const int au = lane >> 4, asx = (arow >> 1) & 3;
    const uint32_t aaddrh0 = Aslot + arow * 64 + (((0 + au) ^ asx) * 16);
    const uint32_t aaddrl0 = Aslot + arow * 64 + (((2 + au) ^ asx) * 16);
    const float* bias = (const float*)(sm + S_B);
    float* hsl = (float*)(sm + S_H + warp * 4608);  // 32 edges x 36 floats

    const long long* e64 = (const long long*)eidx;
    const int* e32 = (const int*)eidx;
    const int is64 = g_is64;

    for (int tile = blockIdx.x * WPB + warp; tile < NTILES; tile += gridDim.x * WPB) {
        const int ebase = tile * 32;
        // thread = edge: load src + dst
        int s, dt;
        if (is64) { s = (int)e64[ebase + lane]; dt = (int)e64[NEDGES + ebase + lane]; }
        else      { s = e32[ebase + lane];      dt = e32[NEDGES + ebase + lane]; }
        // ---- stage A row (64B = [Ah|Al], swizzled) + h row (36-stride, 16B aligned)
        {
            const float4* ep = (const float4*)(eattr + (size_t)(ebase + lane) * 16);
            float4 y0 = ep[0], y1 = ep[1], y2 = ep[2], y3 = ep[3];
            float f[16] = {y0.x, y0.y, y0.z, y0.w, y1.x, y1.y, y1.z, y1.w,
                           y2.x, y2.y, y2.z, y2.w, y3.x, y3.y, y3.z, y3.w};
            uint32_t hp[8], lp[8];
            #pragma unroll
            for (int j = 0; j < 8; j++) {
                __nv_bfloat16 h0 = __float2bfloat16(f[2 * j]);
                __nv_bfloat16 h1 = __float2bfloat16(f[2 * j + 1]);
                __nv_bfloat16 l0 = __float2bfloat16(f[2 * j] - __bfloat162float(h0));
                __nv_bfloat16 l1 = __float2bfloat16(f[2 * j + 1] - __bfloat162float(h1));
                hp[j] = bp2(h0, h1);
                lp[j] = bp2(l0, l1);
            }
            unsigned char* ab = sm + S_A + warp * 2048 + lane * 64;
            const int sx = (lane >> 1) & 3;
            *(uint4*)(ab + ((0 ^ sx) * 16)) = make_uint4(hp[0], hp[1], hp[2], hp[3]);
            *(uint4*)(ab + ((1 ^ sx) * 16)) = make_uint4(hp[4], hp[5], hp[6], hp[7]);
            *(uint4*)(ab + ((2 ^ sx) * 16)) = make_uint4(lp[0], lp[1], lp[2], lp[3]);
            *(uint4*)(ab + ((3 ^ sx) * 16)) = make_uint4(lp[4], lp[5], lp[6], lp[7]);
            const float4* hp4 = (const float4*)(g_h + (size_t)s * CW);
            float4* hd = (float4*)(hsl + lane * 36);
            #pragma unroll
            for (int j = 0; j < 8; j++) hd[j] = hp4[j];
        }
        const int dA = __shfl_sync(0xFFFFFFFFu, dt, grp);
        const int dB = __shfl_sync(0xFFFFFFFFu, dt, grp + 8);
        const int dC = __shfl_sync(0xFFFFFFFFu, dt, grp + 16);
        const int dD = __shfl_sync(0xFFFFFFFFu, dt, grp + 24);
        __syncwarp();

        uint32_t aFh0[4], aFl0[4], aFh1[4], aFl1[4];
        ldsm4(aFh0, aaddrh0);
        ldsm4(aFl0, aaddrl0);
        ldsm4(aFh1, aaddrh0 + 1024);
        ldsm4(aFl1, aaddrl0 + 1024);

        float msg[32];
        #pragma unroll
        for (int i = 0; i < 32; i++) msg[i] = 0.f;

        uint32_t bB = bB0;
        const float* bp = bias + 2 * q4;
        float hp0 = 0.f, hm0 = 0.f, hp1 = 0.f, hm1 = 0.f;
        float hp2 = 0.f, hm2 = 0.f, hp3 = 0.f, hm3 = 0.f;
        #pragma unroll 4
        for (int chunk = 0; chunk < 128; chunk++) {
            if ((chunk & 3) == 0) {
                const int c = chunk >> 2;
                float h0 = hsl[grp * 36 + c];
                float h1 = hsl[(grp + 8) * 36 + c];
                float h2 = hsl[(grp + 16) * 36 + c];
                float h3 = hsl[(grp + 24) * 36 + c];
                hp0 = 0.505f * h0; hm0 = 0.495f * h0;
                hp1 = 0.505f * h1; hm1 = 0.495f * h1;
                hp2 = 0.505f * h2; hm2 = 0.495f * h2;
                hp3 = 0.505f * h3; hm3 = 0.495f * h3;
            }
            uint32_t B0[4];
            ldsm4(B0, bB);
            bB += 512;
            float2 bv = *(const float2*)bp;
            bp += 8;
            float d0[4], d1[4];
            mma16816(d0, aFh0, B0 + 0, bv.x, bv.y, bv.x, bv.y);
            mma16816(d1, aFh1, B0 + 0, bv.x, bv.y, bv.x, bv.y);
            mma16816(d0, aFl0, B0 + 0, d0[0], d0[1], d0[2], d0[3]);
            mma16816(d1, aFl1, B0 + 0, d1[0], d1[1], d1[2], d1[3]);
            mma16816(d0, aFh0, B0 + 2, d0[0], d0[1], d0[2], d0[3]);
            mma16816(d1, aFh1, B0 + 2, d1[0], d1[1], d1[2], d1[3]);
            const int p = chunk & 3;
            msg[p * 2 + 0]      = fmaf(hp0, d0[0], fmaf(hm0, fabsf(d0[0]), msg[p * 2 + 0]));
            msg[p * 2 + 1]      = fmaf(hp0, d0[1], fmaf(hm0, fabsf(d0[1]), msg[p * 2 + 1]));
            msg[8 + p * 2 + 0]  = fmaf(hp1, d0[2], fmaf(hm1, fabsf(d0[2]), msg[8 + p * 2 + 0]));
            msg[8 + p * 2 + 1]  = fmaf(hp1, d0[3], fmaf(hm1, fabsf(d0[3]), msg[8 + p * 2 + 1]));
            msg[16 + p * 2 + 0] = fmaf(hp2, d1[0], fmaf(hm2, fabsf(d1[0]), msg[16 + p * 2 + 0]));
            msg[16 + p * 2 + 1] = fmaf(hp2, d1[1], fmaf(hm2, fabsf(d1[1]), msg[16 + p * 2 + 1]));
            msg[24 + p * 2 + 0] = fmaf(hp3, d1[2], fmaf(hm3, fabsf(d1[2]), msg[24 + p * 2 + 0]));
            msg[24 + p * 2 + 1] = fmaf(hp3, d1[3], fmaf(hm3, fabsf(d1[3]), msg[24 + p * 2 + 1]));
        }
        float* aA = g_aggr + (size_t)dA * CW;
        float* aB = g_aggr + (size_t)dB * CW;
        float* aC = g_aggr + (size_t)dC * CW;
        float* aD = g_aggr + (size_t)dD * CW;
        #pragma unroll
        for (int p = 0; p < 4; p++) {
            const int o = p * 8 + 2 * q4;
            atomicAdd(aA + o, msg[p * 2]);
            atomicAdd(aA + o + 1, msg[p * 2 + 1]);
            atomicAdd(aB + o, msg[8 + p * 2]);
            atomicAdd(aB + o + 1, msg[8 + p * 2 + 1]);
            atomicAdd(aC + o, msg[16 + p * 2]);
            atomicAdd(aC + o + 1, msg[16 + p * 2 + 1]);
            atomicAdd(aD + o, msg[24 + p * 2]);
            atomicAdd(aD + o + 1, msg[24 + p * 2 + 1]);
        }
        __syncwarp();  // A/h slots reused next tile
    }
}

// ---- kernel 3: out = lrelu(aggr + h@W_root + b_conv) @ W_out + b_out ----
__global__ void k_out(const float* __restrict__ Wr, const float* __restrict__ bc,
                      const float* __restrict__ Wo, const float* __restrict__ bo,
                      float* __restrict__ out) {
    __shared__ float Wrs[CW * CW];
    __shared__ float Wos[CW];
    __shared__ float bcs[CW];
    for (int i = threadIdx.x; i < CW * CW; i += blockDim.x) Wrs[i] = Wr[i];
    if (threadIdx.x < CW) { Wos[threadIdx.x] = Wo[threadIdx.x]; bcs[threadIdx.x] = bc[threadIdx.x]; }
    __syncthreads();
    int gw = (blockIdx.x * blockDim.x + threadIdx.x) >> 5;
    int lane = threadIdx.x & 31;
    if (gw >= NNODES) return;
    float r = g_aggr[(size_t)gw * CW + lane] + bcs[lane];
    const float4* hp = (const float4*)(g_h + (size_t)gw * CW);
    #pragma unroll
    for (int c4 = 0; c4 < CW / 4; c4++) {
        float4 h4 = hp[c4];
        int c = c4 * 4;
        r = fmaf(h4.x, Wrs[(c + 0) * CW + lane], r);
        r = fmaf(h4.y, Wrs[(c + 1) * CW + lane], r);
        r = fmaf(h4.z, Wrs[(c + 2) * CW + lane], r);
        r = fmaf(h4.w, Wrs[(c + 3) * CW + lane], r);
    }
    float t = lrelu(r) * Wos[lane];
    #pragma unroll
    for (int off = 16; off; off >>= 1) t += __shfl_xor_sync(0xFFFFFFFFu, t, off);
    if (lane == 0) out[gw] = t + bo[0];
}

extern "C" void kernel_launch(void* const* d_in, const int* in_sizes, int n_in,
                              void* d_out, int out_size) {
    const float* x     = (const float*)d_in[0];
    const void*  ei    = d_in[1];
    const float* ea    = (const float*)d_in[2];
    const float* Win   = (const float*)d_in[3];
    const float* bin   = (const float*)d_in[4];
    const float* Wedge = (const float*)d_in[5];
    const float* bedge = (const float*)d_in[6];
    const float* Wroot = (const float*)d_in[7];
    const float* bconv = (const float*)d_in[8];
    const float* Wout  = (const float*)d_in[9];
    const float* bout  = (const float*)d_in[10];
    float* out = (float*)d_out;

    cudaFuncSetAttribute(k_edge, cudaFuncAttributeMaxDynamicSharedMemorySize, S_TOTAL);

    k_in<<<(6250 * 32 + 255) / 256, 256>>>(ei, x, Win, bin);
    k_edge<<<148, THREADS, S_TOTAL>>>(ei, ea, Wedge, bedge);
    k_out<<<(NNODES * 32 + 255) / 256, 256>>>(Wroot, bconv, Wout, bout, out);
}

// round 15
// speedup vs baseline: 2.3266x; 1.1215x over previous
#include <cuda_runtime.h>
#include <cuda_bf16.h>
#include <cstdint>

#define NNODES 25000
#define NEDGES 400000
#define FIN 128
#define CW 32
#define WPB 16            // warps per block
#define THREADS 512
#define NTILES 12500      // 32-edge tiles

// persistent scratch (no allocs allowed)
__device__ float g_h[NNODES * CW];
__device__ float g_aggr[NNODES * CW];
__device__ int g_is64;
__device__ int g_tick;     // work-stealing ticket (reset by k_in each launch)

__device__ __forceinline__ float lrelu(float v) {
    return fmaxf(v, 0.f) + 0.01f * fminf(v, 0.f);
}
__device__ __forceinline__ uint32_t bp2(__nv_bfloat16 a, __nv_bfloat16 b) {
    return ((uint32_t)__bfloat16_as_ushort(b) << 16) | __bfloat16_as_ushort(a);
}
__device__ __forceinline__ uint32_t smem_u32(const void* p) {
    uint32_t a;
    asm("{ .reg .u64 t; cvta.to.shared.u64 t,%1; cvt.u32.u64 %0,t; }" : "=r"(a) : "l"(p));
    return a;
}
__device__ __forceinline__ void ldsm4(uint32_t* r, uint32_t addr) {
    asm volatile("ldmatrix.sync.aligned.m8n8.x4.shared.b16 {%0,%1,%2,%3},[%4];"
                 : "=r"(r[0]), "=r"(r[1]), "=r"(r[2]), "=r"(r[3]) : "r"(addr));
}
__device__ __forceinline__ void mma16816(float* d, const uint32_t* a, const uint32_t* b,
                                         float c0, float c1, float c2, float c3) {
    asm volatile("mma.sync.aligned.m16n8k16.row.col.f32.bf16.bf16.f32 "
                 "{%0,%1,%2,%3},{%4,%5,%6,%7},{%8,%9},{%10,%11,%12,%13};"
                 : "=f"(d[0]), "=f"(d[1]), "=f"(d[2]), "=f"(d[3])
                 : "r"(a[0]), "r"(a[1]), "r"(a[2]), "r"(a[3]), "r"(b[0]), "r"(b[1]),
                   "f"(c0), "f"(c1), "f"(c2), "f"(c3));
}

// k_edge smem layout (bytes)
#define S_W 0                        // W' 1024 rows x 64B ([Wh|Wl]) = 65536
#define S_B 65536                    // bias f32[1024] = 4096
#define S_A 69632                    // A tiles: WPB x 2048B (32 edges x 64B)
#define S_H (S_A + WPB * 2048)       // h rows: WPB x 32 x 36 floats
#define S_TOTAL (S_H + WPB * 4608)

// ---- kernel 1: h = lrelu(x @ W_in + b_in); zeros g_aggr; detect dtype; reset ticket ----
// block = 384 thr stages 48 node rows (24KB) to smem; warp computes 4 nodes from smem.
#define KIN_T 384
#define KIN_N 48
__global__ void __launch_bounds__(KIN_T) k_in(const void* __restrict__ ei,
                                              const float* __restrict__ x,
                                              const float* __restrict__ Win,
                                              const float* __restrict__ bin) {
    if (blockIdx.x == 0 && threadIdx.x == 0) {
        g_tick = 0;
        const unsigned long long* p = (const unsigned long long*)ei;
        int ok = 1;
        #pragma unroll
        for (int i = 0; i < 16; i++)
            if (p[i] >= (unsigned long long)NNODES) ok = 0;
        g_is64 = ok;  // int32 read as u64 has nonzero high word w.h.p.
    }
    __shared__ float Ws[FIN * CW];   // 16KB
    __shared__ float xs[KIN_N * FIN]; // 24KB
    __shared__ float bs[CW];
    for (int i = threadIdx.x; i < FIN * CW; i += KIN_T) Ws[i] = Win[i];
    if (threadIdx.x < CW) bs[threadIdx.x] = bin[threadIdx.x];
    const int nbase = blockIdx.x * KIN_N;
    // bulk coalesced stage of x rows
    for (int i = threadIdx.x; i < KIN_N * (FIN / 4); i += KIN_T) {
        int row = i >> 5, f4 = i & 31;
        int n = nbase + row;
        float4 v = make_float4(0.f, 0.f, 0.f, 0.f);
        if (n < NNODES) v = ((const float4*)(x + (size_t)n * FIN))[f4];
        ((float4*)xs)[i] = v;
    }
    __syncthreads();

    const int wid = threadIdx.x >> 5, lane = threadIdx.x & 31;
    const int r0 = wid * 4;
    float acc0 = bs[lane], acc1 = acc0, acc2 = acc0, acc3 = acc0;
    const float4* x0 = (const float4*)(xs + (r0 + 0) * FIN);
    const float4* x1 = (const float4*)(xs + (r0 + 1) * FIN);
    const float4* x2 = (const float4*)(xs + (r0 + 2) * FIN);
    const float4* x3 = (const float4*)(xs + (r0 + 3) * FIN);
    #pragma unroll 8
    for (int k4 = 0; k4 < FIN / 4; k4++) {
        float4 a = x0[k4], b = x1[k4], c = x2[k4], d = x3[k4];
        float w0 = Ws[(k4 * 4 + 0) * CW + lane];
        float w1 = Ws[(k4 * 4 + 1) * CW + lane];
        float w2 = Ws[(k4 * 4 + 2) * CW + lane];
        float w3 = Ws[(k4 * 4 + 3) * CW + lane];
        acc0 = fmaf(a.x, w0, acc0); acc0 = fmaf(a.y, w1, acc0);
        acc0 = fmaf(a.z, w2, acc0); acc0 = fmaf(a.w, w3, acc0);
        acc1 = fmaf(b.x, w0, acc1); acc1 = fmaf(b.y, w1, acc1);
        acc1 = fmaf(b.z, w2, acc1); acc1 = fmaf(b.w, w3, acc1);
        acc2 = fmaf(c.x, w0, acc2); acc2 = fmaf(c.y, w1, acc2);
        acc2 = fmaf(c.z, w2, acc2); acc2 = fmaf(c.w, w3, acc2);
        acc3 = fmaf(d.x, w0, acc3); acc3 = fmaf(d.y, w1, acc3);
        acc3 = fmaf(d.z, w2, acc3); acc3 = fmaf(d.w, w3, acc3);
    }
    const int n0 = nbase + r0;
    if (n0 + 0 < NNODES) { g_h[(n0 + 0) * CW + lane] = lrelu(acc0); g_aggr[(n0 + 0) * CW + lane] = 0.f; }
    if (n0 + 1 < NNODES) { g_h[(n0 + 1) * CW + lane] = lrelu(acc1); g_aggr[(n0 + 1) * CW + lane] = 0.f; }
    if (n0 + 2 < NNODES) { g_h[(n0 + 2) * CW + lane] = lrelu(acc2); g_aggr[(n0 + 2) * CW + lane] = 0.f; }
    if (n0 + 3 < NNODES) { g_h[(n0 + 3) * CW + lane] = lrelu(acc3); g_aggr[(n0 + 3) * CW + lane] = 0.f; }
}

// ---- kernel 2: HMMA edge stage, 32 edges per warp-tile, work-stealing tickets ----
// Per 8n-chunk: 1 ldsm.x4 B [Wh|Wl] + 1 bias LDS.64 feed 6 MMAs (2 independent
// 3-chains): d = Ah*Wh + bias; d += Al*Wh; d += Ah*Wl.
// Epilogue: msg += (0.505h)*d + (0.495h)*|d|. Scatter-atomics at tile end.
__global__ void __launch_bounds__(THREADS, 1) k_edge(const void* __restrict__ eidx,
                                                     const float* __restrict__ eattr,
                                                     const float* __restrict__ Wedge,
                                                     const float* __restrict__ bedge) {
    extern __shared__ __align__(128) unsigned char sm[];
    const uint32_t smb = smem_u32(sm);
    const int tid = threadIdx.x, lane = tid & 31, warp = tid >> 5;

    // ---- build W' + bias (once per block)
    for (int n = tid; n < 1024; n += THREADS) {
        uint32_t hp8[8], lp8[8];
        #pragma unroll
        for (int q = 0; q < 8; q++) {
            float w0 = Wedge[(2 * q) * 1024 + n];
            float w1 = Wedge[(2 * q + 1) * 1024 + n];
            __nv_bfloat16 h0 = __float2bfloat16(w0);
            __nv_bfloat16 h1 = __float2bfloat16(w1);
            __nv_bfloat16 l0 = __float2bfloat16(w0 - __bfloat162float(h0));
            __nv_bfloat16 l1 = __float2bfloat16(w1 - __bfloat162float(h1));
            hp8[q] = bp2(h0, h1);
            lp8[q] = bp2(l0, l1);
        }
        unsigned char* wr = sm + S_W + n * 64;
        const int sx = (n >> 1) & 3;
        *(uint4*)(wr + ((0 ^ sx) * 16)) = make_uint4(hp8[0], hp8[1], hp8[2], hp8[3]);
        *(uint4*)(wr + ((1 ^ sx) * 16)) = make_uint4(hp8[4], hp8[5], hp8[6], hp8[7]);
        *(uint4*)(wr + ((2 ^ sx) * 16)) = make_uint4(lp8[0], lp8[1], lp8[2], lp8[3]);
        *(uint4*)(wr + ((3 ^ sx) * 16)) = make_uint4(lp8[4], lp8[5], lp8[6], lp8[7]);
        ((float*)(sm + S_B))[n] = bedge[n];
    }
    __syncthreads();

    const int q4 = lane & 3, grp = lane >> 2;
    const uint32_t Aslot = smb + S_A + warp * 2048;
    const int br = lane & 7, bu = lane >> 3;
    const uint32_t bB0 = smb + S_W + br * 64 + ((bu ^ ((br >> 1) & 3)) * 16);
    const int arow = (lane & 7) + 8 * ((lane >> 3) & 1);
    const int au = lane >> 4, asx = (arow >> 1) & 3;
    const uint32_t aaddrh0 = Aslot + arow * 64 + (((0 + au) ^ asx) * 16);
    const uint32_t aaddrl0 = Aslot + arow * 64 + (((2 + au) ^ asx) * 16);
    const float* bias = (const float*)(sm + S_B);
    float* hsl = (float*)(sm + S_H + warp * 4608);  // 32 edges x 36 floats

    const long long* e64 = (const long long*)eidx;
    const int* e32 = (const int*)eidx;
    const int is64 = g_is64;

    // ---- work-stealing: grab first tile + its edge indices
    int tile;
    if (lane == 0) tile = atomicAdd(&g_tick, 1);
    tile = __shfl_sync(0xFFFFFFFFu, tile, 0);
    int s = 0, dt = 0;
    if (tile < NTILES) {
        const int idx = tile * 32 + lane;
        if (is64) { s = (int)e64[idx]; dt = (int)e64[NEDGES + idx]; }
        else      { s = e32[idx];      dt = e32[NEDGES + idx]; }
    }

    while (tile < NTILES) {
        const int ebase = tile * 32;
        // ---- stage A row (64B = [Ah|Al], swizzled) + h row
        {
            const float4* ep = (const float4*)(eattr + (size_t)(ebase + lane) * 16);
            float4 y0 = ep[0], y1 = ep[1], y2 = ep[2], y3 = ep[3];
            float f[16] = {y0.x, y0.y, y0.z, y0.w, y1.x, y1.y, y1.z, y1.w,
                           y2.x, y2.y, y2.z, y2.w, y3.x, y3.y, y3.z, y3.w};
            uint32_t hp[8], lp[8];
            #pragma unroll
            for (int j = 0; j < 8; j++) {
                __nv_bfloat16 h0 = __float2bfloat16(f[2 * j]);
                __nv_bfloat16 h1 = __float2bfloat16(f[2 * j + 1]);
                __nv_bfloat16 l0 = __float2bfloat16(f[2 * j] - __bfloat162float(h0));
                __nv_bfloat16 l1 = __float2bfloat16(f[2 * j + 1] - __bfloat162float(h1));
                hp[j] = bp2(h0, h1);
                lp[j] = bp2(l0, l1);
            }
            unsigned char* ab = sm + S_A + warp * 2048 + lane * 64;
            const int sx = (lane >> 1) & 3;
            *(uint4*)(ab + ((0 ^ sx) * 16)) = make_uint4(hp[0], hp[1], hp[2], hp[3]);
            *(uint4*)(ab + ((1 ^ sx) * 16)) = make_uint4(hp[4], hp[5], hp[6], hp[7]);
            *(uint4*)(ab + ((2 ^ sx) * 16)) = make_uint4(lp[0], lp[1], lp[2], lp[3]);
            *(uint4*)(ab + ((3 ^ sx) * 16)) = make_uint4(lp[4], lp[5], lp[6], lp[7]);
            const float4* hp4 = (const float4*)(g_h + (size_t)s * CW);
            float4* hd = (float4*)(hsl + lane * 36);
            #pragma unroll
            for (int j = 0; j < 8; j++) hd[j] = hp4[j];
        }
        const int dA = __shfl_sync(0xFFFFFFFFu, dt, grp);
        const int dB = __shfl_sync(0xFFFFFFFFu, dt, grp + 8);
        const int dC = __shfl_sync(0xFFFFFFFFu, dt, grp + 16);
        const int dD = __shfl_sync(0xFFFFFFFFu, dt, grp + 24);
        __syncwarp();

        // ---- prefetch next ticket + its edge indices (completes under mainloop)
        int tnext;
        if (lane == 0) tnext = atomicAdd(&g_tick, 1);
        tnext = __shfl_sync(0xFFFFFFFFu, tnext, 0);
        int sn = 0, dn = 0;
        if (tnext < NTILES) {
            const int idx = tnext * 32 + lane;
            if (is64) { sn = (int)e64[idx]; dn = (int)e64[NEDGES + idx]; }
            else      { sn = e32[idx];      dn = e32[NEDGES + idx]; }
        }

        uint32_t aFh0[4], aFl0[4], aFh1[4], aFl1[4];
        ldsm4(aFh0, aaddrh0);
        ldsm4(aFl0, aaddrl0);
        ldsm4(aFh1, aaddrh0 + 1024);
        ldsm4(aFl1, aaddrl0 + 1024);

        float msg[32];
        #pragma unroll
        for (int i = 0; i < 32; i++) msg[i] = 0.f;

        uint32_t bB = bB0;
        const float* bp = bias + 2 * q4;
        float hp0 = 0.f, hm0 = 0.f, hp1 = 0.f, hm1 = 0.f;
        float hp2 = 0.f, hm2 = 0.f, hp3 = 0.f, hm3 = 0.f;
        #pragma unroll 4
        for (int chunk = 0; chunk < 128; chunk++) {
            if ((chunk & 3) == 0) {
                const int c = chunk >> 2;
                float h0 = hsl[grp * 36 + c];
                float h1 = hsl[(grp + 8) * 36 + c];
                float h2 = hsl[(grp + 16) * 36 + c];
                float h3 = hsl[(grp + 24) * 36 + c];
                hp0 = 0.505f * h0; hm0 = 0.495f * h0;
                hp1 = 0.505f * h1; hm1 = 0.495f * h1;
                hp2 = 0.505f * h2; hm2 = 0.495f * h2;
                hp3 = 0.505f * h3; hm3 = 0.495f * h3;
            }
            uint32_t B0[4];
            ldsm4(B0, bB);
            bB += 512;
            float2 bv = *(const float2*)bp;
            bp += 8;
            float d0[4], d1[4];
            mma16816(d0, aFh0, B0 + 0, bv.x, bv.y, bv.x, bv.y);
            mma16816(d1, aFh1, B0 + 0, bv.x, bv.y, bv.x, bv.y);
            mma16816(d0, aFl0, B0 + 0, d0[0], d0[1], d0[2], d0[3]);
            mma16816(d1, aFl1, B0 + 0, d1[0], d1[1], d1[2], d1[3]);
            mma16816(d0, aFh0, B0 + 2, d0[0], d0[1], d0[2], d0[3]);
            mma16816(d1, aFh1, B0 + 2, d1[0], d1[1], d1[2], d1[3]);
            const int p = chunk & 3;
            msg[p * 2 + 0]      = fmaf(hp0, d0[0], fmaf(hm0, fabsf(d0[0]), msg[p * 2 + 0]));
            msg[p * 2 + 1]      = fmaf(hp0, d0[1], fmaf(hm0, fabsf(d0[1]), msg[p * 2 + 1]));
            msg[8 + p * 2 + 0]  = fmaf(hp1, d0[2], fmaf(hm1, fabsf(d0[2]), msg[8 + p * 2 + 0]));
            msg[8 + p * 2 + 1]  = fmaf(hp1, d0[3], fmaf(hm1, fabsf(d0[3]), msg[8 + p * 2 + 1]));
            msg[16 + p * 2 + 0] = fmaf(hp2, d1[0], fmaf(hm2, fabsf(d1[0]), msg[16 + p * 2 + 0]));
            msg[16 + p * 2 + 1] = fmaf(hp2, d1[1], fmaf(hm2, fabsf(d1[1]), msg[16 + p * 2 + 1]));
            msg[24 + p * 2 + 0] = fmaf(hp3, d1[2], fmaf(hm3, fabsf(d1[2]), msg[24 + p * 2 + 0]));
            msg[24 + p * 2 + 1] = fmaf(hp3, d1[3], fmaf(hm3, fabsf(d1[3]), msg[24 + p * 2 + 1]));
        }
        float* aA = g_aggr + (size_t)dA * CW;
        float* aB = g_aggr + (size_t)dB * CW;
        float* aC = g_aggr + (size_t)dC * CW;
        float* aD = g_aggr + (size_t)dD * CW;
        #pragma unroll
        for (int p = 0; p < 4; p++) {
            const int o = p * 8 + 2 * q4;
            atomicAdd(aA + o, msg[p * 2]);
            atomicAdd(aA + o + 1, msg[p * 2 + 1]);
            atomicAdd(aB + o, msg[8 + p * 2]);
            atomicAdd(aB + o + 1, msg[8 + p * 2 + 1]);
            atomicAdd(aC + o, msg[16 + p * 2]);
            atomicAdd(aC + o + 1, msg[16 + p * 2 + 1]);
            atomicAdd(aD + o, msg[24 + p * 2]);
            atomicAdd(aD + o + 1, msg[24 + p * 2 + 1]);
        }
        __syncwarp();  // A/h slots reused next tile
        tile = tnext; s = sn; dt = dn;
    }
}

// ---- kernel 3: out = lrelu(aggr + h@W_root + b_conv) @ W_out + b_out ----
__global__ void k_out(const float* __restrict__ Wr, const float* __restrict__ bc,
                      const float* __restrict__ Wo, const float* __restrict__ bo,
                      float* __restrict__ out) {
    __shared__ float Wrs[CW * CW];
    __shared__ float Wos[CW];
    __shared__ float bcs[CW];
    for (int i = threadIdx.x; i < CW * CW; i += blockDim.x) Wrs[i] = Wr[i];
    if (threadIdx.x < CW) { Wos[threadIdx.x] = Wo[threadIdx.x]; bcs[threadIdx.x] = bc[threadIdx.x]; }
    __syncthreads();
    int gw = (blockIdx.x * blockDim.x + threadIdx.x) >> 5;
    int lane = threadIdx.x & 31;
    if (gw >= NNODES) return;
    float r = g_aggr[(size_t)gw * CW + lane] + bcs[lane];
    const float4* hp = (const float4*)(g_h + (size_t)gw * CW);
    #pragma unroll
    for (int c4 = 0; c4 < CW / 4; c4++) {
        float4 h4 = hp[c4];
        int c = c4 * 4;
        r = fmaf(h4.x, Wrs[(c + 0) * CW + lane], r);
        r = fmaf(h4.y, Wrs[(c + 1) * CW + lane], r);
        r = fmaf(h4.z, Wrs[(c + 2) * CW + lane], r);
        r = fmaf(h4.w, Wrs[(c + 3) * CW + lane], r);
    }
    float t = lrelu(r) * Wos[lane];
    #pragma unroll
    for (int off = 16; off; off >>= 1) t += __shfl_xor_sync(0xFFFFFFFFu, t, off);
    if (lane == 0) out[gw] = t + bo[0];
}

extern "C" void kernel_launch(void* const* d_in, const int* in_sizes, int n_in,
                              void* d_out, int out_size) {
    const float* x     = (const float*)d_in[0];
    const void*  ei    = d_in[1];
    const float* ea    = (const float*)d_in[2];
    const float* Win   = (const float*)d_in[3];
    const float* bin   = (const float*)d_in[4];
    const float* Wedge = (const float*)d_in[5];
    const float* bedge = (const float*)d_in[6];
    const float* Wroot = (const float*)d_in[7];
    const float* bconv = (const float*)d_in[8];
    const float* Wout  = (const float*)d_in[9];
    const float* bout  = (const float*)d_in[10];
    float* out = (float*)d_out;

    cudaFuncSetAttribute(k_edge, cudaFuncAttributeMaxDynamicSharedMemorySize, S_TOTAL);

    k_in<<<(NNODES + KIN_N - 1) / KIN_N, KIN_T>>>(ei, x, Win, bin);
    k_edge<<<148, THREADS, S_TOTAL>>>(ei, ea, Wedge, bedge);
    k_out<<<(NNODES * 32 + 255) / 256, 256>>>(Wroot, bconv, Wout, bout, out);
}